// round 2
// baseline (speedup 1.0000x reference)
#include <cuda_runtime.h>
#include <cstdint>
#include <climits>
#include <math.h>

#define VOCAB 128000
#define BATCH 256
#define NT 512
#define CAND 2048

// ---------------- scratch (static device globals; no allocations) ----------------
__device__ float    g_rowMax[BATCH];
__device__ int      g_rowArgmax[BATCH];
__device__ float    g_rowZ[BATCH];
__device__ float    g_hist[BATCH][4096];
__device__ unsigned g_vbBits[BATCH];
__device__ int      g_tieMin[BATCH];

// ---------------- helpers ----------------
__device__ __forceinline__ float fdiv_rn(float a, float b) { return __fdiv_rn(a, b); }

// monotone (ascending) ordered-uint key for float
__device__ __forceinline__ unsigned okey(float s) {
    unsigned bb = __float_as_uint(s);
    return (bb & 0x80000000u) ? ~bb : (bb | 0x80000000u);
}

__device__ __forceinline__ unsigned rotl32(unsigned x, int r) { return __funnelshift_l(x, x, r); }

// JAX *partitionable* threefry2x32, key (0, 42).
// Element i of a flat draw: counter = uint64 i -> lanes (hi=0, lo=i).
// x0 = hi + ks0 = 0 ; x1 = lo + ks1 = i + 42 ; 20 rounds ; bits = x0 ^ x1.
// ks = {0, 42, 0^42^0x1BD11BDA = 0x1BD11BF0}
__device__ __forceinline__ float gumbel_at(unsigned i) {
    unsigned x0 = 0u;
    unsigned x1 = i + 42u;
#define TFR(r) { x0 += x1; x1 = rotl32(x1, r); x1 ^= x0; }
    TFR(13) TFR(15) TFR(26) TFR(6)   x0 += 42u;          x1 += 0x1BD11BF1u; // ks1, ks2+1
    TFR(17) TFR(29) TFR(16) TFR(24)  x0 += 0x1BD11BF0u;  x1 += 2u;          // ks2, ks0+2
    TFR(13) TFR(15) TFR(26) TFR(6)   /* x0 += ks0=0 */   x1 += 45u;         // ks0, ks1+3
    TFR(17) TFR(29) TFR(16) TFR(24)  x0 += 42u;          x1 += 0x1BD11BF4u; // ks1, ks2+4
    TFR(13) TFR(15) TFR(26) TFR(6)   x0 += 0x1BD11BF0u;  x1 += 5u;          // ks2, ks0+5
#undef TFR
    unsigned bits = x0 ^ x1;
    float f = __uint_as_float((bits >> 9) | 0x3f800000u) - 1.0f;
    float u = fmaxf(f, 1.17549435e-38f);   // minval = float32 tiny
    return -logf(-logf(u));
}

// ---------------- K1: row max + first-occurrence argmax (raw logits) ----------------
__global__ void k1_rowmax(const float* __restrict__ logits) {
    int b = blockIdx.x, tid = threadIdx.x;
    const float* row = logits + (size_t)b * VOCAB;
    float m = -INFINITY; int mi = 0;
    for (int v = tid; v < VOCAB; v += NT) {
        float x = row[v];
        if (x > m) { m = x; mi = v; }
    }
    __shared__ float sm[NT];
    __shared__ int   si[NT];
    sm[tid] = m; si[tid] = mi;
    __syncthreads();
    for (int s = NT / 2; s > 0; s >>= 1) {
        if (tid < s) {
            float om = sm[tid + s]; int oi = si[tid + s];
            if (om > sm[tid] || (om == sm[tid] && oi < si[tid])) { sm[tid] = om; si[tid] = oi; }
        }
        __syncthreads();
    }
    if (tid == 0) { g_rowMax[b] = sm[0]; g_rowArgmax[b] = si[0]; }
}

// ---------------- K2: Z = sum exp(s - smax), e-weighted level-1 histogram ----------------
__global__ void k2_hist(const float* __restrict__ logits, const float* __restrict__ temps) {
    int b = blockIdx.x, tid = threadIdx.x;
    __shared__ float h[4096];
    for (int i = tid; i < 4096; i += NT) h[i] = 0.f;
    float t = temps[b];
    float tt = (t == 0.f) ? 1.f : t;
    float smax = fdiv_rn(g_rowMax[b], tt);
    __syncthreads();
    const float* row = logits + (size_t)b * VOCAB;
    float z = 0.f;
    for (int v = tid; v < VOCAB; v += NT) {
        float s = fdiv_rn(row[v], tt);
        float e = expf(s - smax);
        z += e;
        atomicAdd(&h[okey(s) >> 20], e);
    }
    __shared__ float sz[NT];
    sz[tid] = z;
    __syncthreads();
    for (int s2 = NT / 2; s2 > 0; s2 >>= 1) { if (tid < s2) sz[tid] += sz[tid + s2]; __syncthreads(); }
    if (tid == 0) g_rowZ[b] = sz[0];
    for (int i = tid; i < 4096; i += NT) g_hist[b][i] = h[i];
}

// ---------------- K3: find boundary value vb + tie cut index ----------------
__global__ void k3_select(const float* __restrict__ logits, const float* __restrict__ temps,
                          const float* __restrict__ topps) {
    int b = blockIdx.x, tid = threadIdx.x;
    __shared__ float h[4096];
    __shared__ float part[NT];
    __shared__ float s_cs[CAND];
    __shared__ int   s_ci[CAND];
    __shared__ float s_ce[CAND];
    __shared__ int   s_cnt;
    __shared__ int   sBin;
    __shared__ float sA;
    __shared__ int   sDone;

    float t = temps[b];
    float tt = (t == 0.f) ? 1.f : t;
    float smax = fdiv_rn(g_rowMax[b], tt);
    float p = topps[b]; p = fminf(fmaxf(p, 0.f), 1.f);
    float T = p * g_rowZ[b];
    const float* row = logits + (size_t)b * VOCAB;

    for (int i = tid; i < 4096; i += NT) h[i] = g_hist[b][i];
    __syncthreads();

    // --- stage 1: crossing bin in descending-value order (desc pos j <-> bin 4095-j)
    {
        float acc = 0.f;
        for (int jj = 0; jj < 8; jj++) acc += h[4095 - (tid * 8 + jj)];
        part[tid] = acc;
    }
    __syncthreads();
    if (tid == 0) {
        float cum = 0.f; int fb = -1; float fA = 0.f;
        for (int s = 0; s < NT && fb < 0; s++) {
            if (part[s] > 0.f && cum + part[s] > T) {
                for (int jj = 0; jj < 8; jj++) {
                    int bin = 4095 - (s * 8 + jj); float hh = h[bin];
                    if (hh > 0.f && cum + hh > T) { fb = bin; fA = cum; break; }
                    cum += hh;
                }
            } else cum += part[s];
        }
        sBin = fb; sA = fA; sDone = (fb < 0);
    }
    __syncthreads();
    if (sDone) {  // everything kept
        if (tid == 0) { g_vbBits[b] = 0xFF800000u; g_tieMin[b] = INT_MIN; }
        return;
    }
    int B1 = sBin; float A1 = sA;
    __syncthreads();

    // --- stage 2: level-2 histogram restricted to bin B1
    for (int i = tid; i < 4096; i += NT) h[i] = 0.f;
    __syncthreads();
    for (int v = tid; v < VOCAB; v += NT) {
        float s = fdiv_rn(row[v], tt);
        unsigned m = okey(s);
        if ((int)(m >> 20) == B1) atomicAdd(&h[(m >> 8) & 0xFFFu], expf(s - smax));
    }
    __syncthreads();
    {
        float acc = 0.f;
        for (int jj = 0; jj < 8; jj++) acc += h[4095 - (tid * 8 + jj)];
        part[tid] = acc;
    }
    __syncthreads();
    if (tid == 0) {
        float cum = A1; int fb = -1; float fA = A1;
        for (int s = 0; s < NT && fb < 0; s++) {
            if (part[s] > 0.f && cum + part[s] > T) {
                for (int jj = 0; jj < 8; jj++) {
                    int bin = 4095 - (s * 8 + jj); float hh = h[bin];
                    if (hh > 0.f && cum + hh > T) { fb = bin; fA = cum; break; }
                    cum += hh;
                }
            } else cum += part[s];
        }
        if (fb < 0) {  // rounding edge: lowest-valued nonempty sub-bin
            cum = A1; int last = -1; float lastA = A1;
            for (int j = 0; j < 4096; j++) {
                int bin = 4095 - j; float hh = h[bin];
                if (hh > 0.f) { last = bin; lastA = cum; }
                cum += hh;
            }
            fb = last; fA = lastA;
        }
        sBin = fb; sA = fA;
    }
    __syncthreads();
    int B2 = sBin; float A2 = sA;
    unsigned pref = ((unsigned)B1 << 12) | (unsigned)B2;

    // --- stage 3: gather boundary candidates (share 24-bit ordered-key prefix)
    if (tid == 0) s_cnt = 0;
    __syncthreads();
    for (int v = tid; v < VOCAB; v += NT) {
        float s = fdiv_rn(row[v], tt);
        unsigned m = okey(s);
        if ((m >> 8) == pref) {
            int pos = atomicAdd(&s_cnt, 1);
            if (pos < CAND) { s_cs[pos] = s; s_ci[pos] = v; s_ce[pos] = expf(s - smax); }
        }
    }
    __syncthreads();

    // --- stage 4: serial fine walk with exact tie semantics (value desc, index desc)
    if (tid == 0) {
        int n = min(s_cnt, CAND);
        for (int i = 1; i < n; i++) {
            float sv = s_cs[i]; int iv = s_ci[i]; float ev = s_ce[i]; int j = i - 1;
            while (j >= 0 && (s_cs[j] < sv || (s_cs[j] == sv && s_ci[j] < iv))) {
                s_cs[j + 1] = s_cs[j]; s_ci[j + 1] = s_ci[j]; s_ce[j + 1] = s_ce[j]; j--;
            }
            s_cs[j + 1] = sv; s_ci[j + 1] = iv; s_ce[j + 1] = ev;
        }
        bool globalFirst = (A2 == 0.f);   // rank-0 is always kept
        float cum = A2; int lastKept = -1;
        for (int i = 0; i < n; i++) {
            cum += s_ce[i];
            bool kept = (cum <= T) || (globalFirst && i == 0);
            if (kept) lastKept = i; else break;
        }
        unsigned vbB; int tieMin;
        if (lastKept < 0) {               // boundary just above candidates: kept iff s > cs[0]
            vbB = __float_as_uint(s_cs[0]); tieMin = INT_MAX;
        } else {
            float vL = s_cs[lastKept];
            bool partial = (lastKept + 1 < n) && (s_cs[lastKept + 1] == vL);
            vbB = __float_as_uint(vL);
            tieMin = partial ? s_ci[lastKept] : INT_MIN;
        }
        g_vbBits[b] = vbB; g_tieMin[b] = tieMin;
    }
}

// ---------------- K4: fused kept-mask + keptE + threefry/gumbel argmax + outputs ----------------
__global__ void k4_sample(const float* __restrict__ logits, const float* __restrict__ temps,
                          float* __restrict__ out, int half_out) {
    int b = blockIdx.x, tid = threadIdx.x;
    float t = temps[b];
    float tt = (t == 0.f) ? 1.f : t;
    float smax = fdiv_rn(g_rowMax[b], tt);
    float vb = __uint_as_float(g_vbBits[b]);
    int tieMin = g_tieMin[b];
    const float* row = logits + (size_t)b * VOCAB;
    unsigned base = (unsigned)b * (unsigned)VOCAB;

    float keptE = 0.f;
    float best = -INFINITY; int bi = INT_MAX;
    for (int v = tid; v < VOCAB; v += NT) {
        float s = fdiv_rn(row[v], tt);
        bool kept = (s > vb) || (s == vb && v >= tieMin);
        if (kept) {
            keptE += expf(s - smax);
            float val = s + gumbel_at(base + (unsigned)v);
            if (val > best || (val == best && v < bi)) { best = val; bi = v; }
        }
    }
    __shared__ float se[NT];
    __shared__ float sbv[NT];
    __shared__ int   sbi[NT];
    se[tid] = keptE; sbv[tid] = best; sbi[tid] = bi;
    __syncthreads();
    for (int s2 = NT / 2; s2 > 0; s2 >>= 1) {
        if (tid < s2) {
            se[tid] += se[tid + s2];
            float ov = sbv[tid + s2]; int oi = sbi[tid + s2];
            if (ov > sbv[tid] || (ov == sbv[tid] && oi < sbi[tid])) { sbv[tid] = ov; sbi[tid] = oi; }
        }
        __syncthreads();
    }
    if (tid == 0) {
        float logz = smax + logf(se[0]);
        int tok; float lp;
        if (t == 0.f) {
            tok = g_rowArgmax[b];
            float s = fdiv_rn(row[tok], tt);
            bool kept = (s > vb) || (s == vb && tok >= tieMin);
            lp = kept ? (s - logz) : -INFINITY;
        } else {
            tok = sbi[0];
            float s = fdiv_rn(row[tok], tt);
            lp = s - logz;
        }
        out[b] = (float)tok;
        out[half_out + b] = lp;
    }
}

// ---------------- launch ----------------
extern "C" void kernel_launch(void* const* d_in, const int* in_sizes, int n_in,
                              void* d_out, int out_size) {
    const float* logits = (const float*)d_in[0];
    const float* temps  = (const float*)d_in[1];
    const float* topps  = (const float*)d_in[2];
    float* out = (float*)d_out;
    int half_out = out_size / 2;

    k1_rowmax<<<BATCH, NT>>>(logits);
    k2_hist<<<BATCH, NT>>>(logits, temps);
    k3_select<<<BATCH, NT>>>(logits, temps, topps);
    k4_sample<<<BATCH, NT>>>(logits, temps, out, half_out);
}

// round 3
// speedup vs baseline: 2.9308x; 2.9308x over previous
#include <cuda_runtime.h>
#include <cstdint>
#include <climits>
#include <math.h>

#define VOCAB 128000
#define BATCH 256
#define SEG 8
#define SEGLEN (VOCAB / SEG)     // 16000
#define THR 256
#define CAND 2048

// ---------------- scratch (static device globals; no allocations) ----------------
__device__ unsigned long long g_packMax[BATCH];   // (okey(x)<<32) | ~idx  -> max = (max x, min idx)
__device__ float              g_rowZ[BATCH];
__device__ float              g_hist[BATCH][4096];
__device__ float              g_hist2[BATCH][4096];
__device__ int                g_B1[BATCH];
__device__ float              g_A1[BATCH];
__device__ float              g_T[BATCH];
__device__ int                g_done[BATCH];
__device__ unsigned           g_pref[BATCH];
__device__ float              g_A2[BATCH];
__device__ unsigned           g_vbBits[BATCH];
__device__ int                g_tieMin[BATCH];
__device__ int                g_candCnt[BATCH];
__device__ float              g_cs[BATCH][CAND];
__device__ int                g_ci[BATCH][CAND];
__device__ float              g_keptE[BATCH];
__device__ unsigned long long g_bestPack[BATCH];  // (okey(s+g)<<32) | ~idx

// ---------------- helpers ----------------
__device__ __forceinline__ unsigned okey(float s) {
    unsigned bb = __float_as_uint(s);
    return (bb & 0x80000000u) ? ~bb : (bb | 0x80000000u);
}
__device__ __forceinline__ unsigned rotl32(unsigned x, int r) { return __funnelshift_l(x, x, r); }

// JAX partitionable threefry2x32, key (0,42): x0 = 0, x1 = i + 42, 20 rounds, bits = x0^x1.
__device__ __forceinline__ float gumbel_at(unsigned i) {
    unsigned x0 = 0u;
    unsigned x1 = i + 42u;
#define TFR(r) { x0 += x1; x1 = rotl32(x1, r); x1 ^= x0; }
    TFR(13) TFR(15) TFR(26) TFR(6)   x0 += 42u;          x1 += 0x1BD11BF1u;
    TFR(17) TFR(29) TFR(16) TFR(24)  x0 += 0x1BD11BF0u;  x1 += 2u;
    TFR(13) TFR(15) TFR(26) TFR(6)   /* +0 */            x1 += 45u;
    TFR(17) TFR(29) TFR(16) TFR(24)  x0 += 42u;          x1 += 0x1BD11BF4u;
    TFR(13) TFR(15) TFR(26) TFR(6)   x0 += 0x1BD11BF0u;  x1 += 5u;
#undef TFR
    unsigned bits = x0 ^ x1;
    float f = __uint_as_float((bits >> 9) | 0x3f800000u) - 1.0f;
    float u = fmaxf(f, 1.17549435e-38f);
    return -logf(-logf(u));   // precise logf: winner margin demands it
}

__device__ __forceinline__ float row_rcp(float t) {
    float tt = (t == 0.f) ? 1.f : t;
    return __fdiv_rn(1.0f, tt);
}
__device__ __forceinline__ float row_smax(int b, float rcp) {
    unsigned hk = (unsigned)(g_packMax[b] >> 32);
    float xmax = __uint_as_float((hk & 0x80000000u) ? (hk & 0x7FFFFFFFu) : ~hk);
    return xmax * rcp;
}

// ---------------- K0: zero scratch ----------------
__global__ void k0_init() {
    int i = blockIdx.x * blockDim.x + threadIdx.x;
    int stride = gridDim.x * blockDim.x;
    for (int j = i; j < BATCH * 4096; j += stride) {
        ((float*)g_hist)[j] = 0.f;
        ((float*)g_hist2)[j] = 0.f;
    }
    if (i < BATCH) {
        g_packMax[i] = 0ull; g_rowZ[i] = 0.f; g_keptE[i] = 0.f;
        g_bestPack[i] = 0ull; g_candCnt[i] = 0;
    }
}

// ---------------- K1: row max + argmax (8 segs/row, packed atomicMax) ----------------
__global__ void k1_max(const float* __restrict__ logits) {
    int b = blockIdx.y, seg = blockIdx.x, tid = threadIdx.x;
    const float* row = logits + (size_t)b * VOCAB;
    int lo = seg * SEGLEN, hi = lo + SEGLEN;
    float m = -INFINITY; int mi = 0;
    for (int v = lo + tid; v < hi; v += THR) {
        float x = row[v];
        if (x > m) { m = x; mi = v; }
    }
    unsigned long long pk = ((unsigned long long)okey(m) << 32) | (unsigned)(~mi);
    __shared__ unsigned long long sp[THR];
    sp[tid] = pk; __syncthreads();
    for (int s = THR / 2; s > 0; s >>= 1) {
        if (tid < s) sp[tid] = max(sp[tid], sp[tid + s]);
        __syncthreads();
    }
    if (tid == 0) atomicMax(&g_packMax[b], sp[0]);
}

// ---------------- K2: Z + e-weighted level-1 histogram ----------------
__global__ void k2_hist(const float* __restrict__ logits, const float* __restrict__ temps) {
    int b = blockIdx.y, seg = blockIdx.x, tid = threadIdx.x;
    __shared__ float h[4096];
    for (int i = tid; i < 4096; i += THR) h[i] = 0.f;
    float rcp = row_rcp(temps[b]);
    float smax = row_smax(b, rcp);
    __syncthreads();
    const float* row = logits + (size_t)b * VOCAB;
    int lo = seg * SEGLEN, hi = lo + SEGLEN;
    float z = 0.f;
    for (int v = lo + tid; v < hi; v += THR) {
        float s = row[v] * rcp;
        float e = __expf(s - smax);
        z += e;
        atomicAdd(&h[okey(s) >> 20], e);
    }
    __shared__ float sz[THR];
    sz[tid] = z; __syncthreads();
    for (int s2 = THR / 2; s2 > 0; s2 >>= 1) { if (tid < s2) sz[tid] += sz[tid + s2]; __syncthreads(); }
    if (tid == 0) atomicAdd(&g_rowZ[b], sz[0]);
    for (int i = tid; i < 4096; i += THR) if (h[i] != 0.f) atomicAdd(&g_hist[b][i], h[i]);
}

// ---------------- K3a: level-1 select ----------------
__global__ void k3a_sel1(const float* __restrict__ topps) {
    int b = blockIdx.x, tid = threadIdx.x;
    __shared__ float h[4096];
    __shared__ float part[THR];
    for (int i = tid; i < 4096; i += THR) h[i] = g_hist[b][i];
    float p = topps[b]; p = fminf(fmaxf(p, 0.f), 1.f);
    float T = p * g_rowZ[b];
    __syncthreads();
    {
        float acc = 0.f;
        for (int jj = 0; jj < 16; jj++) acc += h[4095 - (tid * 16 + jj)];
        part[tid] = acc;
    }
    __syncthreads();
    if (tid == 0) {
        float cum = 0.f; int fb = -1; float fA = 0.f;
        for (int s = 0; s < THR && fb < 0; s++) {
            if (part[s] > 0.f && cum + part[s] > T) {
                for (int jj = 0; jj < 16; jj++) {
                    int bin = 4095 - (s * 16 + jj); float hh = h[bin];
                    if (hh > 0.f && cum + hh > T) { fb = bin; fA = cum; break; }
                    cum += hh;
                }
            } else cum += part[s];
        }
        g_T[b] = T;
        if (fb < 0) {                // all kept
            g_done[b] = 1; g_vbBits[b] = 0xFF800000u; g_tieMin[b] = INT_MIN;
        } else {
            g_done[b] = 0; g_B1[b] = fb; g_A1[b] = fA;
        }
    }
}

// ---------------- K3b: level-2 histogram restricted to B1 ----------------
__global__ void k3b_hist2(const float* __restrict__ logits, const float* __restrict__ temps) {
    int b = blockIdx.y;
    if (g_done[b]) return;
    int seg = blockIdx.x, tid = threadIdx.x;
    float rcp = row_rcp(temps[b]);
    float smax = row_smax(b, rcp);
    int B1 = g_B1[b];
    const float* row = logits + (size_t)b * VOCAB;
    int lo = seg * SEGLEN, hi = lo + SEGLEN;
    for (int v = lo + tid; v < hi; v += THR) {
        float s = row[v] * rcp;
        unsigned m = okey(s);
        if ((int)(m >> 20) == B1)
            atomicAdd(&g_hist2[b][(m >> 8) & 0xFFFu], __expf(s - smax));
    }
}

// ---------------- K3c: level-2 select ----------------
__global__ void k3c_sel2() {
    int b = blockIdx.x, tid = threadIdx.x;
    if (g_done[b]) return;
    __shared__ float h[4096];
    __shared__ float part[THR];
    for (int i = tid; i < 4096; i += THR) h[i] = g_hist2[b][i];
    float T = g_T[b]; float A1 = g_A1[b];
    __syncthreads();
    {
        float acc = 0.f;
        for (int jj = 0; jj < 16; jj++) acc += h[4095 - (tid * 16 + jj)];
        part[tid] = acc;
    }
    __syncthreads();
    if (tid == 0) {
        float cum = A1; int fb = -1; float fA = A1;
        for (int s = 0; s < THR && fb < 0; s++) {
            if (part[s] > 0.f && cum + part[s] > T) {
                for (int jj = 0; jj < 16; jj++) {
                    int bin = 4095 - (s * 16 + jj); float hh = h[bin];
                    if (hh > 0.f && cum + hh > T) { fb = bin; fA = cum; break; }
                    cum += hh;
                }
            } else cum += part[s];
        }
        if (fb < 0) {  // rounding edge: lowest nonempty sub-bin
            cum = A1; int last = -1; float lastA = A1;
            for (int j = 0; j < 4096; j++) {
                int bin = 4095 - j; float hh = h[bin];
                if (hh > 0.f) { last = bin; lastA = cum; }
                cum += hh;
            }
            fb = last; fA = lastA;
        }
        g_pref[b] = ((unsigned)g_B1[b] << 12) | (unsigned)fb;
        g_A2[b] = fA;
    }
}

// ---------------- K3d: gather boundary candidates (24-bit prefix) ----------------
__global__ void k3d_gather(const float* __restrict__ logits, const float* __restrict__ temps) {
    int b = blockIdx.y;
    if (g_done[b]) return;
    int seg = blockIdx.x, tid = threadIdx.x;
    float rcp = row_rcp(temps[b]);
    unsigned pref = g_pref[b];
    const float* row = logits + (size_t)b * VOCAB;
    int lo = seg * SEGLEN, hi = lo + SEGLEN;
    for (int v = lo + tid; v < hi; v += THR) {
        float s = row[v] * rcp;
        if ((okey(s) >> 8) == pref) {
            int pos = atomicAdd(&g_candCnt[b], 1);
            if (pos < CAND) { g_cs[b][pos] = s; g_ci[b][pos] = v; }
        }
    }
}

// ---------------- K3e: serial fine walk (exact tie semantics) ----------------
__global__ void k3e_walk(const float* __restrict__ temps) {
    int b = blockIdx.x, tid = threadIdx.x;
    if (g_done[b]) return;
    __shared__ float s_cs[CAND];
    __shared__ int   s_ci[CAND];
    int n = min(g_candCnt[b], CAND);
    for (int i = tid; i < n; i += THR) { s_cs[i] = g_cs[b][i]; s_ci[i] = g_ci[b][i]; }
    __syncthreads();
    if (tid == 0) {
        float rcp = row_rcp(temps[b]);
        float smax = row_smax(b, rcp);
        float T = g_T[b], A2 = g_A2[b];
        // insertion sort desc by (value desc, index desc)
        for (int i = 1; i < n; i++) {
            float sv = s_cs[i]; int iv = s_ci[i]; int j = i - 1;
            while (j >= 0 && (s_cs[j] < sv || (s_cs[j] == sv && s_ci[j] < iv))) {
                s_cs[j + 1] = s_cs[j]; s_ci[j + 1] = s_ci[j]; j--;
            }
            s_cs[j + 1] = sv; s_ci[j + 1] = iv;
        }
        bool globalFirst = (A2 == 0.f);
        float cum = A2; int lastKept = -1;
        for (int i = 0; i < n; i++) {
            cum += __expf(s_cs[i] - smax);
            bool kept = (cum <= T) || (globalFirst && i == 0);
            if (kept) lastKept = i; else break;
        }
        unsigned vbB; int tieMin;
        if (lastKept < 0) {
            vbB = __float_as_uint(s_cs[0]); tieMin = INT_MAX;
        } else {
            float vL = s_cs[lastKept];
            bool partial = (lastKept + 1 < n) && (s_cs[lastKept + 1] == vL);
            vbB = __float_as_uint(vL);
            tieMin = partial ? s_ci[lastKept] : INT_MIN;
        }
        g_vbBits[b] = vbB; g_tieMin[b] = tieMin;
    }
}

// ---------------- K4: kept-mask + keptE + threefry/gumbel argmax (segmented) ----------------
__global__ void k4_sample(const float* __restrict__ logits, const float* __restrict__ temps) {
    int b = blockIdx.y, seg = blockIdx.x, tid = threadIdx.x;
    float t = temps[b];
    float rcp = row_rcp(t);
    float smax = row_smax(b, rcp);
    float vb = __uint_as_float(g_vbBits[b]);
    int tieMin = g_tieMin[b];
    const float* row = logits + (size_t)b * VOCAB;
    unsigned base = (unsigned)b * (unsigned)VOCAB;
    bool greedy = (t == 0.f);
    int lo = seg * SEGLEN, hi = lo + SEGLEN;

    float keptE = 0.f;
    unsigned long long bp = 0ull;
    for (int v = lo + tid; v < hi; v += THR) {
        float s = row[v] * rcp;
        bool kept = (s > vb) || (s == vb && v >= tieMin);
        if (kept) {
            keptE += __expf(s - smax);
            if (!greedy) {
                float val = s + gumbel_at(base + (unsigned)v);
                unsigned long long pk = ((unsigned long long)okey(val) << 32) | (unsigned)(~v);
                bp = max(bp, pk);
            }
        }
    }
    __shared__ float se[THR];
    __shared__ unsigned long long sp[THR];
    se[tid] = keptE; sp[tid] = bp;
    __syncthreads();
    for (int s2 = THR / 2; s2 > 0; s2 >>= 1) {
        if (tid < s2) { se[tid] += se[tid + s2]; sp[tid] = max(sp[tid], sp[tid + s2]); }
        __syncthreads();
    }
    if (tid == 0) {
        atomicAdd(&g_keptE[b], se[0]);
        if (!greedy) atomicMax(&g_bestPack[b], sp[0]);
    }
}

// ---------------- K4b: finalize outputs ----------------
__global__ void k4b_final(const float* __restrict__ logits, const float* __restrict__ temps,
                          float* __restrict__ out, int half_out) {
    int b = threadIdx.x;
    if (b >= BATCH) return;
    float t = temps[b];
    float rcp = row_rcp(t);
    float smax = row_smax(b, rcp);
    float logz = smax + logf(g_keptE[b]);
    const float* row = logits + (size_t)b * VOCAB;
    int tok; float lp;
    if (t == 0.f) {
        tok = VOCAB - 1 - (int)(unsigned)(g_packMax[b] & 0xFFFFFFFFull);
        // recompute: packed ~idx -> idx
        tok = (int)(~(unsigned)(g_packMax[b] & 0xFFFFFFFFull));
        float s = row[tok] * rcp;
        float vb = __uint_as_float(g_vbBits[b]);
        bool kept = (s > vb) || (s == vb && tok >= g_tieMin[b]);
        lp = kept ? (s - logz) : -INFINITY;
    } else {
        tok = (int)(~(unsigned)(g_bestPack[b] & 0xFFFFFFFFull));
        float s = row[tok] * rcp;
        lp = s - logz;
    }
    out[b] = (float)tok;
    out[half_out + b] = lp;
}

// ---------------- launch ----------------
extern "C" void kernel_launch(void* const* d_in, const int* in_sizes, int n_in,
                              void* d_out, int out_size) {
    const float* logits = (const float*)d_in[0];
    const float* temps  = (const float*)d_in[1];
    const float* topps  = (const float*)d_in[2];
    float* out = (float*)d_out;
    int half_out = out_size / 2;

    dim3 segGrid(SEG, BATCH);
    k0_init<<<1024, 512>>>();
    k1_max<<<segGrid, THR>>>(logits);
    k2_hist<<<segGrid, THR>>>(logits, temps);
    k3a_sel1<<<BATCH, THR>>>(topps);
    k3b_hist2<<<segGrid, THR>>>(logits, temps);
    k3c_sel2<<<BATCH, THR>>>();
    k3d_gather<<<segGrid, THR>>>(logits, temps);
    k3e_walk<<<BATCH, THR>>>(temps);
    k4_sample<<<segGrid, THR>>>(logits, temps);
    k4b_final<<<1, BATCH>>>(logits, temps, out, half_out);
}

// round 4
// speedup vs baseline: 3.1666x; 1.0805x over previous
#include <cuda_runtime.h>
#include <cstdint>
#include <climits>
#include <math.h>

#define VOCAB 128000
#define BATCH 256
#define SEG 8
#define SEGLEN (VOCAB / SEG)     // 16000 (divisible by 4)
#define THR 256
#define CAP 16384                // max gathered elements of crossing bin B1
#define FINE 2048                // max fine (24-bit-prefix) candidates

// ---------------- scratch (static device globals; no allocations) ----------------
__device__ unsigned long long g_packMax[BATCH];   // (okey(x)<<32) | ~idx
__device__ float              g_rowZ[BATCH];
__device__ float              g_hist[BATCH][4096];
__device__ int                g_B1[BATCH];
__device__ float              g_A1[BATCH];
__device__ float              g_T[BATCH];
__device__ int                g_done[BATCH];
__device__ unsigned           g_vbBits[BATCH];
__device__ int                g_tieMin[BATCH];
__device__ int                g_candCnt[BATCH];
__device__ float              g_cs[BATCH][CAP];
__device__ int                g_ci[BATCH][CAP];
__device__ float              g_keptE[BATCH];
__device__ unsigned long long g_bestPack[BATCH];  // (okey(s+g)<<32) | ~idx

// ---------------- helpers ----------------
__device__ __forceinline__ unsigned okey(float s) {
    unsigned bb = __float_as_uint(s);
    return (bb & 0x80000000u) ? ~bb : (bb | 0x80000000u);
}
__device__ __forceinline__ unsigned rotl32(unsigned x, int r) { return __funnelshift_l(x, x, r); }

// JAX partitionable threefry2x32, key (0,42): x0=0, x1=i+42, 20 rounds, bits = x0^x1.
// Inner log precise (u->1 amplification); outer log fast (abs err <= ~3e-6).
__device__ __forceinline__ float gumbel_at(unsigned i) {
    unsigned x0 = 0u;
    unsigned x1 = i + 42u;
#define TFR(r) { x0 += x1; x1 = rotl32(x1, r); x1 ^= x0; }
    TFR(13) TFR(15) TFR(26) TFR(6)   x0 += 42u;          x1 += 0x1BD11BF1u;
    TFR(17) TFR(29) TFR(16) TFR(24)  x0 += 0x1BD11BF0u;  x1 += 2u;
    TFR(13) TFR(15) TFR(26) TFR(6)   /* +0 */            x1 += 45u;
    TFR(17) TFR(29) TFR(16) TFR(24)  x0 += 42u;          x1 += 0x1BD11BF4u;
    TFR(13) TFR(15) TFR(26) TFR(6)   x0 += 0x1BD11BF0u;  x1 += 5u;
#undef TFR
    unsigned bits = x0 ^ x1;
    float f = __uint_as_float((bits >> 9) | 0x3f800000u) - 1.0f;
    float u = fmaxf(f, 1.17549435e-38f);
    return -__logf(-logf(u));
}

__device__ __forceinline__ float row_rcp(float t) {
    float tt = (t == 0.f) ? 1.f : t;
    return __fdiv_rn(1.0f, tt);
}
__device__ __forceinline__ float row_smax(int b, float rcp) {
    unsigned hk = (unsigned)(g_packMax[b] >> 32);
    float xmax = __uint_as_float((hk & 0x80000000u) ? (hk & 0x7FFFFFFFu) : ~hk);
    return xmax * rcp;
}

// ---------------- K0: zero scratch ----------------
__global__ void k0_init() {
    int i = blockIdx.x * blockDim.x + threadIdx.x;   // exactly BATCH*4096 threads
    ((float*)g_hist)[i] = 0.f;
    if (i < BATCH) {
        g_packMax[i] = 0ull; g_rowZ[i] = 0.f; g_keptE[i] = 0.f;
        g_bestPack[i] = 0ull; g_candCnt[i] = 0;
    }
}

// ---------------- K1: row max + argmax (packed atomicMax) ----------------
__global__ void k1_max(const float* __restrict__ logits) {
    int b = blockIdx.y, seg = blockIdx.x, tid = threadIdx.x;
    const float4* row4 = (const float4*)(logits + (size_t)b * VOCAB + seg * SEGLEN);
    int lo = seg * SEGLEN;
    float m = -INFINITY; int mi = 0;
    for (int i = tid; i < SEGLEN / 4; i += THR) {
        float4 x = row4[i];
        int v = lo + 4 * i;
        if (x.x > m) { m = x.x; mi = v; }
        if (x.y > m) { m = x.y; mi = v + 1; }
        if (x.z > m) { m = x.z; mi = v + 2; }
        if (x.w > m) { m = x.w; mi = v + 3; }
    }
    unsigned long long pk = ((unsigned long long)okey(m) << 32) | (unsigned)(~mi);
    __shared__ unsigned long long sp[THR];
    sp[tid] = pk; __syncthreads();
    for (int s = THR / 2; s > 0; s >>= 1) {
        if (tid < s) sp[tid] = max(sp[tid], sp[tid + s]);
        __syncthreads();
    }
    if (tid == 0) atomicMax(&g_packMax[b], sp[0]);
}

// ---------------- K2: Z + e-weighted level-1 histogram ----------------
__global__ void k2_hist(const float* __restrict__ logits, const float* __restrict__ temps) {
    int b = blockIdx.y, seg = blockIdx.x, tid = threadIdx.x;
    __shared__ float h[4096];
    for (int i = tid; i < 4096; i += THR) h[i] = 0.f;
    float rcp = row_rcp(temps[b]);
    float smax = row_smax(b, rcp);
    __syncthreads();
    const float4* row4 = (const float4*)(logits + (size_t)b * VOCAB + seg * SEGLEN);
    float z = 0.f;
    for (int i = tid; i < SEGLEN / 4; i += THR) {
        float4 x = row4[i];
        #pragma unroll
        for (int j = 0; j < 4; j++) {
            float xv = (j == 0) ? x.x : (j == 1) ? x.y : (j == 2) ? x.z : x.w;
            float s = xv * rcp;
            float e = __expf(s - smax);
            z += e;
            atomicAdd(&h[okey(s) >> 20], e);
        }
    }
    __shared__ float sz[THR];
    sz[tid] = z; __syncthreads();
    for (int s2 = THR / 2; s2 > 0; s2 >>= 1) { if (tid < s2) sz[tid] += sz[tid + s2]; __syncthreads(); }
    if (tid == 0) atomicAdd(&g_rowZ[b], sz[0]);
    for (int i = tid; i < 4096; i += THR) if (h[i] != 0.f) atomicAdd(&g_hist[b][i], h[i]);
}

// ---------------- K3a: level-1 select (parallel scan) ----------------
__global__ void k3a_sel1(const float* __restrict__ topps) {
    int b = blockIdx.x, tid = threadIdx.x;
    __shared__ float h[4096];
    __shared__ float warpSum[8], warpEx[8];
    __shared__ int s_seg;
    for (int i = tid; i < 4096; i += THR) h[i] = g_hist[b][i];
    float p = topps[b]; p = fminf(fmaxf(p, 0.f), 1.f);
    float T = p * g_rowZ[b];
    if (tid == 0) s_seg = THR;
    __syncthreads();
    float part = 0.f;
    #pragma unroll
    for (int jj = 0; jj < 16; jj++) part += h[4095 - (tid * 16 + jj)];
    int lane = tid & 31, wid = tid >> 5;
    float sc = part;
    for (int o = 1; o < 32; o <<= 1) { float v = __shfl_up_sync(~0u, sc, o); if (lane >= o) sc += v; }
    float ex = sc - part;
    if (lane == 31) warpSum[wid] = sc;
    __syncthreads();
    if (wid == 0) {
        float ws = (lane < 8) ? warpSum[lane] : 0.f;
        float s2 = ws;
        for (int o = 1; o < 8; o <<= 1) { float v = __shfl_up_sync(0xFFFFFFFFu, s2, o); if (lane >= o) s2 += v; }
        if (lane < 8) warpEx[lane] = s2 - ws;
    }
    __syncthreads();
    float P = ex + warpEx[wid];
    bool flag = (part > 0.f) && (P + part > T);
    if (flag) atomicMin(&s_seg, tid);
    __syncthreads();
    if (tid == 0) {
        g_T[b] = T;
        if (s_seg == THR) { g_done[b] = 1; g_vbBits[b] = 0xFF800000u; g_tieMin[b] = INT_MIN; }
        else g_done[b] = 0;
    }
    if (tid == s_seg) {
        float cum = P;
        for (int jj = 0; jj < 16; jj++) {
            int bin = 4095 - (tid * 16 + jj); float hh = h[bin];
            if (hh > 0.f && cum + hh > T) { g_B1[b] = bin; g_A1[b] = cum; break; }
            cum += hh;
        }
    }
}

// ---------------- K3g: gather all elements of crossing bin B1 ----------------
__global__ void k3g_gather(const float* __restrict__ logits, const float* __restrict__ temps) {
    int b = blockIdx.y;
    if (g_done[b]) return;
    int seg = blockIdx.x, tid = threadIdx.x;
    float rcp = row_rcp(temps[b]);
    int B1 = g_B1[b];
    const float4* row4 = (const float4*)(logits + (size_t)b * VOCAB + seg * SEGLEN);
    int lo = seg * SEGLEN;
    for (int i = tid; i < SEGLEN / 4; i += THR) {
        float4 x = row4[i];
        int v = lo + 4 * i;
        #pragma unroll
        for (int j = 0; j < 4; j++) {
            float xv = (j == 0) ? x.x : (j == 1) ? x.y : (j == 2) ? x.z : x.w;
            float s = xv * rcp;
            if ((int)(okey(s) >> 20) == B1) {
                int pos = atomicAdd(&g_candCnt[b], 1);
                if (pos < CAP) { g_cs[b][pos] = s; g_ci[b][pos] = v + j; }
            }
        }
    }
}

// ---------------- K3s: level-2 select + fine tie walk (one block/row) ----------------
__global__ void k3s_select(const float* __restrict__ temps) {
    int b = blockIdx.x, tid = threadIdx.x;
    if (g_done[b]) return;
    __shared__ float h[4096];
    __shared__ float warpSum[8], warpEx[8];
    __shared__ int s_seg, s_B2;
    __shared__ float s_A2;
    __shared__ float fs[FINE];
    __shared__ int   fi[FINE];
    __shared__ int   fcnt;
    for (int i = tid; i < 4096; i += THR) h[i] = 0.f;
    if (tid == 0) { fcnt = 0; s_seg = THR; }
    __syncthreads();
    int n = min(g_candCnt[b], CAP);
    float rcp = row_rcp(temps[b]);
    float smax = row_smax(b, rcp);
    for (int i = tid; i < n; i += THR) {
        float s = g_cs[b][i];
        atomicAdd(&h[(okey(s) >> 8) & 0xFFFu], __expf(s - smax));
    }
    __syncthreads();
    float T = g_T[b], A1 = g_A1[b];
    float part = 0.f;
    #pragma unroll
    for (int jj = 0; jj < 16; jj++) part += h[4095 - (tid * 16 + jj)];
    int lane = tid & 31, wid = tid >> 5;
    float sc = part;
    for (int o = 1; o < 32; o <<= 1) { float v = __shfl_up_sync(~0u, sc, o); if (lane >= o) sc += v; }
    float ex = sc - part;
    if (lane == 31) warpSum[wid] = sc;
    __syncthreads();
    if (wid == 0) {
        float ws = (lane < 8) ? warpSum[lane] : 0.f;
        float s2 = ws;
        for (int o = 1; o < 8; o <<= 1) { float v = __shfl_up_sync(0xFFFFFFFFu, s2, o); if (lane >= o) s2 += v; }
        if (lane < 8) warpEx[lane] = s2 - ws;
    }
    __syncthreads();
    float P = A1 + ex + warpEx[wid];
    bool flag = (part > 0.f) && (P + part > T);
    if (flag) atomicMin(&s_seg, tid);
    __syncthreads();
    if (tid == s_seg) {
        float cum = P;
        for (int jj = 0; jj < 16; jj++) {
            int bin = 4095 - (tid * 16 + jj); float hh = h[bin];
            if (hh > 0.f && cum + hh > T) { s_B2 = bin; s_A2 = cum; break; }
            cum += hh;
        }
    }
    if (tid == 0 && s_seg == THR) {   // rounding edge: lowest nonempty sub-bin
        float cum = A1; int last = -1; float lastA = A1;
        for (int j = 0; j < 4096; j++) {
            int bin = 4095 - j; float hh = h[bin];
            if (hh > 0.f) { last = bin; lastA = cum; }
            cum += hh;
        }
        s_B2 = last; s_A2 = lastA;
    }
    __syncthreads();
    unsigned pref = ((unsigned)g_B1[b] << 12) | (unsigned)s_B2;
    float A2 = s_A2;
    for (int i = tid; i < n; i += THR) {
        float s = g_cs[b][i];
        if ((okey(s) >> 8) == pref) {
            int pos = atomicAdd(&fcnt, 1);
            if (pos < FINE) { fs[pos] = s; fi[pos] = g_ci[b][i]; }
        }
    }
    __syncthreads();
    if (tid == 0) {
        int m = min(fcnt, FINE);
        for (int i = 1; i < m; i++) {       // sort desc by (value desc, index desc)
            float sv = fs[i]; int iv = fi[i]; int j = i - 1;
            while (j >= 0 && (fs[j] < sv || (fs[j] == sv && fi[j] < iv))) {
                fs[j + 1] = fs[j]; fi[j + 1] = fi[j]; j--;
            }
            fs[j + 1] = sv; fi[j + 1] = iv;
        }
        bool globalFirst = (A2 == 0.f);     // rank-0 always kept
        float cum = A2; int lastKept = -1;
        for (int i = 0; i < m; i++) {
            cum += __expf(fs[i] - smax);
            bool kept = (cum <= T) || (globalFirst && i == 0);
            if (kept) lastKept = i; else break;
        }
        unsigned vbB; int tieMin;
        if (lastKept < 0) {
            vbB = __float_as_uint(fs[0]); tieMin = INT_MAX;
        } else {
            float vL = fs[lastKept];
            bool partial = (lastKept + 1 < m) && (fs[lastKept + 1] == vL);
            vbB = __float_as_uint(vL);
            tieMin = partial ? fi[lastKept] : INT_MIN;
        }
        g_vbBits[b] = vbB; g_tieMin[b] = tieMin;
    }
}

// ---------------- K4: kept-mask + keptE + threefry/gumbel argmax ----------------
__global__ void k4_sample(const float* __restrict__ logits, const float* __restrict__ temps) {
    int b = blockIdx.y, seg = blockIdx.x, tid = threadIdx.x;
    float t = temps[b];
    float rcp = row_rcp(t);
    float smax = row_smax(b, rcp);
    float vb = __uint_as_float(g_vbBits[b]);
    int tieMin = g_tieMin[b];
    const float4* row4 = (const float4*)(logits + (size_t)b * VOCAB + seg * SEGLEN);
    unsigned base = (unsigned)b * (unsigned)VOCAB + (unsigned)(seg * SEGLEN);
    bool greedy = (t == 0.f);

    float keptE = 0.f;
    unsigned long long bp = 0ull;
    for (int i = tid; i < SEGLEN / 4; i += THR) {
        float4 x = row4[i];
        unsigned v = 4u * (unsigned)i;
        #pragma unroll
        for (int j = 0; j < 4; j++) {
            float xv = (j == 0) ? x.x : (j == 1) ? x.y : (j == 2) ? x.z : x.w;
            float s = xv * rcp;
            bool kept = (s > vb) || (s == vb && (int)(v + j + (base - (unsigned)b * (unsigned)VOCAB)) >= tieMin);
            if (kept) {
                keptE += __expf(s - smax);
                if (!greedy) {
                    unsigned idx = base + v + j;
                    float val = s + gumbel_at(idx);
                    int tok = (int)(idx - (unsigned)b * (unsigned)VOCAB);
                    unsigned long long pk = ((unsigned long long)okey(val) << 32) | (unsigned)(~tok);
                    bp = max(bp, pk);
                }
            }
        }
    }
    __shared__ float se[THR];
    __shared__ unsigned long long sp[THR];
    se[tid] = keptE; sp[tid] = bp;
    __syncthreads();
    for (int s2 = THR / 2; s2 > 0; s2 >>= 1) {
        if (tid < s2) { se[tid] += se[tid + s2]; sp[tid] = max(sp[tid], sp[tid + s2]); }
        __syncthreads();
    }
    if (tid == 0) {
        atomicAdd(&g_keptE[b], se[0]);
        if (!greedy) atomicMax(&g_bestPack[b], sp[0]);
    }
}

// ---------------- K4b: finalize outputs ----------------
__global__ void k4b_final(const float* __restrict__ logits, const float* __restrict__ temps,
                          float* __restrict__ out, int half_out) {
    int b = threadIdx.x;
    if (b >= BATCH) return;
    float t = temps[b];
    float rcp = row_rcp(t);
    float smax = row_smax(b, rcp);
    float logz = smax + logf(g_keptE[b]);
    const float* row = logits + (size_t)b * VOCAB;
    int tok; float lp;
    if (t == 0.f) {
        tok = (int)(~(unsigned)(g_packMax[b] & 0xFFFFFFFFull));
        float s = row[tok] * rcp;
        float vb = __uint_as_float(g_vbBits[b]);
        bool kept = (s > vb) || (s == vb && tok >= g_tieMin[b]);
        lp = kept ? (s - logz) : -INFINITY;
    } else {
        tok = (int)(~(unsigned)(g_bestPack[b] & 0xFFFFFFFFull));
        float s = row[tok] * rcp;
        lp = s - logz;
    }
    out[b] = (float)tok;
    out[half_out + b] = lp;
}

// ---------------- launch ----------------
extern "C" void kernel_launch(void* const* d_in, const int* in_sizes, int n_in,
                              void* d_out, int out_size) {
    const float* logits = (const float*)d_in[0];
    const float* temps  = (const float*)d_in[1];
    const float* topps  = (const float*)d_in[2];
    float* out = (float*)d_out;
    int half_out = out_size / 2;

    dim3 segGrid(SEG, BATCH);
    k0_init<<<(BATCH * 4096) / 512, 512>>>();
    k1_max<<<segGrid, THR>>>(logits);
    k2_hist<<<segGrid, THR>>>(logits, temps);
    k3a_sel1<<<BATCH, THR>>>(topps);
    k3g_gather<<<segGrid, THR>>>(logits, temps);
    k3s_select<<<BATCH, THR>>>(temps);
    k4_sample<<<segGrid, THR>>>(logits, temps);
    k4b_final<<<1, BATCH>>>(logits, temps, out, half_out);
}

// round 5
// speedup vs baseline: 3.3984x; 1.0732x over previous
#include <cuda_runtime.h>
#include <cstdint>
#include <climits>
#include <math.h>

#define VOCAB 128000
#define BATCH 256
#define SEG 8
#define SEGLEN (VOCAB / SEG)          // 16000
#define THR 256
#define NQ (SEGLEN / 4)               // 4000 float4 per segment
#define NIT ((NQ + THR - 1) / THR)    // 16 (padded uniform loop for ballots)
#define CAP 16384
#define FINE 1024

// ---------------- scratch ----------------
__device__ unsigned long long g_packMax[BATCH];   // (okey(x)<<32) | ~idx
__device__ float              g_rowZ[BATCH];
__device__ float              g_hist[BATCH][4096];
__device__ int                g_B1[BATCH];
__device__ float              g_A1[BATCH];
__device__ float              g_T[BATCH];
__device__ int                g_done[BATCH];
__device__ unsigned           g_vbBits[BATCH];
__device__ int                g_tieMin[BATCH];
__device__ int                g_candCnt[BATCH];
__device__ float              g_cs[BATCH][CAP];
__device__ int                g_ci[BATCH][CAP];
__device__ float              g_keptE[BATCH];
__device__ unsigned long long g_bestPack[BATCH];  // (okey(e/w)<<32) | ~idx
__device__ int                g_arr2[BATCH], g_arr3[BATCH], g_arr4[BATCH];

// ---------------- helpers ----------------
__device__ __forceinline__ unsigned okey(float s) {
    unsigned bb = __float_as_uint(s);
    return (bb & 0x80000000u) ? ~bb : (bb | 0x80000000u);
}
__device__ __forceinline__ unsigned rotl32(unsigned x, int r) { return __funnelshift_l(x, x, r); }

// JAX partitionable threefry2x32, key (0,42): x0=0, x1=i+42, 20 rounds, bits=x0^x1.
// Returns w = -log(u) with u = max(tiny, mantissa-uniform). Precise logf (u->1 amplification).
__device__ __forceinline__ float w_at(unsigned i) {
    unsigned x0 = 0u;
    unsigned x1 = i + 42u;
#define TFR(r) { x0 += x1; x1 = rotl32(x1, r); x1 ^= x0; }
    TFR(13) TFR(15) TFR(26) TFR(6)   x0 += 42u;          x1 += 0x1BD11BF1u;
    TFR(17) TFR(29) TFR(16) TFR(24)  x0 += 0x1BD11BF0u;  x1 += 2u;
    TFR(13) TFR(15) TFR(26) TFR(6)   /* +0 */            x1 += 45u;
    TFR(17) TFR(29) TFR(16) TFR(24)  x0 += 42u;          x1 += 0x1BD11BF4u;
    TFR(13) TFR(15) TFR(26) TFR(6)   x0 += 0x1BD11BF0u;  x1 += 5u;
#undef TFR
    unsigned bits = x0 ^ x1;
    float f = __uint_as_float((bits >> 9) | 0x3f800000u) - 1.0f;
    float u = fmaxf(f, 1.17549435e-38f);
    return -logf(u);
}

__device__ __forceinline__ float row_rcp(float t) {
    float tt = (t == 0.f) ? 1.f : t;
    return __fdiv_rn(1.0f, tt);
}
__device__ __forceinline__ float row_smax(int b, float rcp) {
    unsigned hk = (unsigned)(g_packMax[b] >> 32);
    float xmax = __uint_as_float((hk & 0x80000000u) ? (hk & 0x7FFFFFFFu) : ~hk);
    return xmax * rcp;
}

// ---------------- K0: zero scratch ----------------
__global__ void k0_init() {
    int i = blockIdx.x * blockDim.x + threadIdx.x;   // BATCH*4096 threads
    ((float*)g_hist)[i] = 0.f;
    if (i < BATCH) {
        g_packMax[i] = 0ull; g_rowZ[i] = 0.f; g_keptE[i] = 0.f;
        g_bestPack[i] = 0ull; g_candCnt[i] = 0;
        g_arr2[i] = 0; g_arr3[i] = 0; g_arr4[i] = 0;
    }
}

// ---------------- K1: row max + argmax ----------------
__global__ void k1_max(const float* __restrict__ logits) {
    int b = blockIdx.y, seg = blockIdx.x, tid = threadIdx.x;
    const float4* row4 = (const float4*)(logits + (size_t)b * VOCAB + seg * SEGLEN);
    int lo = seg * SEGLEN;
    float m = -INFINITY; int mi = 0;
    for (int i = tid; i < NQ; i += THR) {
        float4 x = row4[i];
        int v = lo + 4 * i;
        if (x.x > m) { m = x.x; mi = v; }
        if (x.y > m) { m = x.y; mi = v + 1; }
        if (x.z > m) { m = x.z; mi = v + 2; }
        if (x.w > m) { m = x.w; mi = v + 3; }
    }
    unsigned long long pk = ((unsigned long long)okey(m) << 32) | (unsigned)(~mi);
    __shared__ unsigned long long sp[THR];
    sp[tid] = pk; __syncthreads();
    for (int s = THR / 2; s > 0; s >>= 1) {
        if (tid < s) sp[tid] = max(sp[tid], sp[tid + s]);
        __syncthreads();
    }
    if (tid == 0) atomicMax(&g_packMax[b], sp[0]);
}

// ---------------- K2: Z + hist ; last block per row runs level-1 select ----------------
__global__ void k2_hist(const float* __restrict__ logits, const float* __restrict__ temps,
                        const float* __restrict__ topps) {
    int b = blockIdx.y, seg = blockIdx.x, tid = threadIdx.x;
    __shared__ float h[4096];
    for (int i = tid; i < 4096; i += THR) h[i] = 0.f;
    float rcp = row_rcp(temps[b]);
    float smax = row_smax(b, rcp);
    __syncthreads();
    const float4* row4 = (const float4*)(logits + (size_t)b * VOCAB + seg * SEGLEN);
    float z = 0.f;
    for (int i = tid; i < NQ; i += THR) {
        float4 x = row4[i];
        #pragma unroll
        for (int j = 0; j < 4; j++) {
            float xv = (j == 0) ? x.x : (j == 1) ? x.y : (j == 2) ? x.z : x.w;
            float s = xv * rcp;
            float e = __expf(s - smax);
            z += e;
            atomicAdd(&h[okey(s) >> 20], e);
        }
    }
    __shared__ float sz[THR];
    sz[tid] = z; __syncthreads();
    for (int s2 = THR / 2; s2 > 0; s2 >>= 1) { if (tid < s2) sz[tid] += sz[tid + s2]; __syncthreads(); }
    if (tid == 0) atomicAdd(&g_rowZ[b], sz[0]);
    for (int i = tid; i < 4096; i += THR) if (h[i] != 0.f) atomicAdd(&g_hist[b][i], h[i]);

    // ----- last-block-per-row: level-1 select -----
    __threadfence();
    __shared__ int s_last;
    if (tid == 0) s_last = (atomicAdd(&g_arr2[b], 1) == SEG - 1);
    __syncthreads();
    if (!s_last) return;
    __threadfence();
    for (int i = tid; i < 4096; i += THR) h[i] = g_hist[b][i];
    float p = topps[b]; p = fminf(fmaxf(p, 0.f), 1.f);
    float T = p * g_rowZ[b];
    __shared__ float warpSum[8], warpEx[8];
    __shared__ int s_seg;
    if (tid == 0) s_seg = THR;
    __syncthreads();
    float part = 0.f;
    #pragma unroll
    for (int jj = 0; jj < 16; jj++) part += h[4095 - (tid * 16 + jj)];
    int lane = tid & 31, wid = tid >> 5;
    float sc = part;
    for (int o = 1; o < 32; o <<= 1) { float v = __shfl_up_sync(~0u, sc, o); if (lane >= o) sc += v; }
    float ex = sc - part;
    if (lane == 31) warpSum[wid] = sc;
    __syncthreads();
    if (wid == 0) {
        float ws = (lane < 8) ? warpSum[lane] : 0.f;
        float s2 = ws;
        for (int o = 1; o < 8; o <<= 1) { float v = __shfl_up_sync(0xFFFFFFFFu, s2, o); if (lane >= o) s2 += v; }
        if (lane < 8) warpEx[lane] = s2 - ws;
    }
    __syncthreads();
    float P = ex + warpEx[wid];
    bool flag = (part > 0.f) && (P + part > T);
    if (flag) atomicMin(&s_seg, tid);
    __syncthreads();
    if (tid == 0) {
        g_T[b] = T;
        if (s_seg == THR) { g_done[b] = 1; g_vbBits[b] = 0xFF800000u; g_tieMin[b] = INT_MIN; }
        else g_done[b] = 0;
    }
    if (tid == s_seg) {
        float cum = P;
        for (int jj = 0; jj < 16; jj++) {
            int bin = 4095 - (tid * 16 + jj); float hh = h[bin];
            if (hh > 0.f && cum + hh > T) { g_B1[b] = bin; g_A1[b] = cum; break; }
            cum += hh;
        }
    }
}

// ---------------- K3g: gather bin-B1 members ; last block runs level-2 select + fine walk ----------------
__global__ void k3g_gather(const float* __restrict__ logits, const float* __restrict__ temps) {
    int b = blockIdx.y;
    if (g_done[b]) return;
    int seg = blockIdx.x, tid = threadIdx.x;
    float rcp = row_rcp(temps[b]);
    float smax = row_smax(b, rcp);
    int B1 = g_B1[b];
    const float4* row4 = (const float4*)(logits + (size_t)b * VOCAB + seg * SEGLEN);
    int lo = seg * SEGLEN;
    for (int i = tid; i < NQ; i += THR) {
        float4 x = row4[i];
        int v = lo + 4 * i;
        #pragma unroll
        for (int j = 0; j < 4; j++) {
            float xv = (j == 0) ? x.x : (j == 1) ? x.y : (j == 2) ? x.z : x.w;
            float s = xv * rcp;
            if ((int)(okey(s) >> 20) == B1) {
                int pos = atomicAdd(&g_candCnt[b], 1);
                if (pos < CAP) { g_cs[b][pos] = s; g_ci[b][pos] = v + j; }
            }
        }
    }

    // ----- last-block-per-row: level-2 select + fine tie walk -----
    __threadfence();
    __shared__ int s_last;
    if (tid == 0) s_last = (atomicAdd(&g_arr3[b], 1) == SEG - 1);
    __syncthreads();
    if (!s_last) return;
    __threadfence();

    __shared__ float h[4096];
    __shared__ float warpSum[8], warpEx[8];
    __shared__ int s_seg, s_B2;
    __shared__ float s_A2;
    __shared__ float fs[FINE];
    __shared__ int   fi[FINE];
    __shared__ int   fcnt;
    for (int i = tid; i < 4096; i += THR) h[i] = 0.f;
    if (tid == 0) { fcnt = 0; s_seg = THR; }
    __syncthreads();
    int n = min(g_candCnt[b], CAP);
    for (int i = tid; i < n; i += THR) {
        float s = g_cs[b][i];
        atomicAdd(&h[(okey(s) >> 8) & 0xFFFu], __expf(s - smax));
    }
    __syncthreads();
    float T = g_T[b], A1 = g_A1[b];
    float part = 0.f;
    #pragma unroll
    for (int jj = 0; jj < 16; jj++) part += h[4095 - (tid * 16 + jj)];
    int lane = tid & 31, wid = tid >> 5;
    float sc = part;
    for (int o = 1; o < 32; o <<= 1) { float v = __shfl_up_sync(~0u, sc, o); if (lane >= o) sc += v; }
    float ex = sc - part;
    if (lane == 31) warpSum[wid] = sc;
    __syncthreads();
    if (wid == 0) {
        float ws = (lane < 8) ? warpSum[lane] : 0.f;
        float s2 = ws;
        for (int o = 1; o < 8; o <<= 1) { float v = __shfl_up_sync(0xFFFFFFFFu, s2, o); if (lane >= o) s2 += v; }
        if (lane < 8) warpEx[lane] = s2 - ws;
    }
    __syncthreads();
    float P = A1 + ex + warpEx[wid];
    bool flag = (part > 0.f) && (P + part > T);
    if (flag) atomicMin(&s_seg, tid);
    __syncthreads();
    if (tid == s_seg) {
        float cum = P;
        for (int jj = 0; jj < 16; jj++) {
            int bin = 4095 - (tid * 16 + jj); float hh = h[bin];
            if (hh > 0.f && cum + hh > T) { s_B2 = bin; s_A2 = cum; break; }
            cum += hh;
        }
    }
    if (tid == 0 && s_seg == THR) {   // rounding edge: lowest nonempty sub-bin
        float cum = A1; int last = -1; float lastA = A1;
        for (int j = 0; j < 4096; j++) {
            int bin = 4095 - j; float hh = h[bin];
            if (hh > 0.f) { last = bin; lastA = cum; }
            cum += hh;
        }
        s_B2 = last; s_A2 = lastA;
    }
    __syncthreads();
    unsigned pref = ((unsigned)g_B1[b] << 12) | (unsigned)s_B2;
    float A2 = s_A2;
    for (int i = tid; i < n; i += THR) {
        float s = g_cs[b][i];
        if ((okey(s) >> 8) == pref) {
            int pos = atomicAdd(&fcnt, 1);
            if (pos < FINE) { fs[pos] = s; fi[pos] = g_ci[b][i]; }
        }
    }
    __syncthreads();
    if (tid == 0) {
        int m = min(fcnt, FINE);
        for (int i = 1; i < m; i++) {       // desc by (value desc, index desc)
            float sv = fs[i]; int iv = fi[i]; int j = i - 1;
            while (j >= 0 && (fs[j] < sv || (fs[j] == sv && fi[j] < iv))) {
                fs[j + 1] = fs[j]; fi[j + 1] = fi[j]; j--;
            }
            fs[j + 1] = sv; fi[j + 1] = iv;
        }
        bool globalFirst = (A2 == 0.f);     // rank-0 always kept
        float cum = A2; int lastKept = -1;
        for (int i = 0; i < m; i++) {
            cum += __expf(fs[i] - smax);
            bool kept = (cum <= T) || (globalFirst && i == 0);
            if (kept) lastKept = i; else break;
        }
        unsigned vbB; int tieMin;
        if (lastKept < 0) {
            vbB = __float_as_uint(fs[0]); tieMin = INT_MAX;
        } else {
            float vL = fs[lastKept];
            bool partial = (lastKept + 1 < m) && (fs[lastKept + 1] == vL);
            vbB = __float_as_uint(vL);
            tieMin = partial ? fi[lastKept] : INT_MIN;
        }
        g_vbBits[b] = vbB; g_tieMin[b] = tieMin;
    }
}

// ---------------- K4: warp-compacted gumbel argmax + keptE ; last block finalizes ----------------
__global__ void k4_sample(const float* __restrict__ logits, const float* __restrict__ temps,
                          float* __restrict__ out, int half_out) {
    int b = blockIdx.y, seg = blockIdx.x, tid = threadIdx.x;
    int lane = tid & 31, wrp = tid >> 5;
    float t = temps[b];
    float rcp = row_rcp(t);
    float smax = row_smax(b, rcp);
    float vb = __uint_as_float(g_vbBits[b]);
    int tieMin = g_tieMin[b];
    bool greedy = (t == 0.f);
    const float4* row4 = (const float4*)(logits + (size_t)b * VOCAB + seg * SEGLEN);
    int lo = seg * SEGLEN;
    unsigned rowbase = (unsigned)b * (unsigned)VOCAB;

    __shared__ float ebuf[8][64];
    __shared__ int   ibuf[8][64];
    float keptE = 0.f;
    float be = 0.f, bw = 1.f; int bi = INT_MAX;   // best = (e, w, idx); score = e/w
    int cnt = 0, done = 0;

    for (int it = 0; it < NIT; it++) {
        int i = tid + it * THR;
        bool valid = (i < NQ);
        float4 x = valid ? row4[i] : make_float4(0.f, 0.f, 0.f, 0.f);
        int v0 = lo + 4 * i;
        #pragma unroll
        for (int j = 0; j < 4; j++) {
            float xv = (j == 0) ? x.x : (j == 1) ? x.y : (j == 2) ? x.z : x.w;
            float s = xv * rcp;
            bool kept = valid && ((s > vb) || (s == vb && (v0 + j) >= tieMin));
            float e = kept ? __expf(s - smax) : 0.f;
            keptE += e;
            if (!greedy) {
                unsigned mask = __ballot_sync(0xFFFFFFFFu, kept);
                if (kept) {
                    int pos = cnt + __popc(mask & ((1u << lane) - 1u));
                    ebuf[wrp][pos & 63] = e; ibuf[wrp][pos & 63] = v0 + j;
                }
                cnt += __popc(mask);
                if (cnt - done >= 32) {
                    __syncwarp();
                    int k = done + lane;
                    float e2 = ebuf[wrp][k & 63]; int i2 = ibuf[wrp][k & 63];
                    float w2 = w_at(rowbase + (unsigned)i2);
                    float lhs = e2 * bw, rhs = be * w2;
                    if (lhs > rhs || (lhs == rhs && i2 < bi)) { be = e2; bw = w2; bi = i2; }
                    done += 32;
                    __syncwarp();
                }
            }
        }
    }
    if (!greedy) {
        __syncwarp();
        int rem = cnt - done;
        if (lane < rem) {
            int k = done + lane;
            float e2 = ebuf[wrp][k & 63]; int i2 = ibuf[wrp][k & 63];
            float w2 = w_at(rowbase + (unsigned)i2);
            float lhs = e2 * bw, rhs = be * w2;
            if (lhs > rhs || (lhs == rhs && i2 < bi)) { be = e2; bw = w2; bi = i2; }
        }
    }

    __shared__ float se[THR];
    __shared__ float rbe[THR], rbw[THR];
    __shared__ int   rbi[THR];
    se[tid] = keptE; rbe[tid] = be; rbw[tid] = bw; rbi[tid] = bi;
    __syncthreads();
    for (int s2 = THR / 2; s2 > 0; s2 >>= 1) {
        if (tid < s2) {
            se[tid] += se[tid + s2];
            float lhs = rbe[tid + s2] * rbw[tid], rhs = rbe[tid] * rbw[tid + s2];
            if (lhs > rhs || (lhs == rhs && rbi[tid + s2] < rbi[tid])) {
                rbe[tid] = rbe[tid + s2]; rbw[tid] = rbw[tid + s2]; rbi[tid] = rbi[tid + s2];
            }
        }
        __syncthreads();
    }
    if (tid == 0) {
        atomicAdd(&g_keptE[b], se[0]);
        if (!greedy && rbi[0] != INT_MAX) {
            float ratio = __fdiv_rn(rbe[0], rbw[0]);
            unsigned long long pk = ((unsigned long long)okey(ratio) << 32) | (unsigned)(~rbi[0]);
            atomicMax(&g_bestPack[b], pk);
        }
    }

    // ----- last-block-per-row: finalize outputs -----
    __threadfence();
    __shared__ int s_last;
    if (tid == 0) s_last = (atomicAdd(&g_arr4[b], 1) == SEG - 1);
    __syncthreads();
    if (!s_last) return;
    if (tid == 0) {
        __threadfence();
        float logz = smax + logf(g_keptE[b]);
        const float* row = logits + (size_t)b * VOCAB;
        int tok; float lp;
        if (greedy) {
            tok = (int)(~(unsigned)(g_packMax[b] & 0xFFFFFFFFull));
            float s = row[tok] * rcp;
            bool kept = (s > vb) || (s == vb && tok >= tieMin);
            lp = kept ? (s - logz) : -INFINITY;
        } else {
            tok = (int)(~(unsigned)(g_bestPack[b] & 0xFFFFFFFFull));
            float s = row[tok] * rcp;
            lp = s - logz;
        }
        out[b] = (float)tok;
        out[half_out + b] = lp;
    }
}

// ---------------- launch ----------------
extern "C" void kernel_launch(void* const* d_in, const int* in_sizes, int n_in,
                              void* d_out, int out_size) {
    const float* logits = (const float*)d_in[0];
    const float* temps  = (const float*)d_in[1];
    const float* topps  = (const float*)d_in[2];
    float* out = (float*)d_out;
    int half_out = out_size / 2;

    dim3 segGrid(SEG, BATCH);
    k0_init<<<(BATCH * 4096) / 512, 512>>>();
    k1_max<<<segGrid, THR>>>(logits);
    k2_hist<<<segGrid, THR>>>(logits, temps, topps);
    k3g_gather<<<segGrid, THR>>>(logits, temps);
    k4_sample<<<segGrid, THR>>>(logits, temps, out, half_out);
}